// round 2
// baseline (speedup 1.0000x reference)
#include <cuda_runtime.h>
#include <cstdint>

// Z gate on qubits (DIM=2): phase diag[n] = (-1)^popc(n & MASK), MASK from
// INDEX=(0,5,10), L=14 -> bits 13, 8, 3. Pure signed copy, HBM-bound.
// x_real, x_imag: [N, B] float32. out: [2, N, B] float32.
// N = 16384, B = 2048. B/4 = 512 float4 per row.

static constexpr int N_ROWS   = 16384;
static constexpr int B_COLS   = 2048;
static constexpr uint32_t MASK = (1u << 13) | (1u << 8) | (1u << 3); // 8456
static constexpr int TOTAL4   = N_ROWS * B_COLS / 4; // 8388608 float4 per plane

__global__ void __launch_bounds__(256) z_phase_kernel(
    const float4* __restrict__ xr,
    const float4* __restrict__ xi,
    float4* __restrict__ outr,
    float4* __restrict__ outi)
{
    int i = blockIdx.x * blockDim.x + threadIdx.x;
    // B/4 = 512 float4 per row -> row = i >> 9
    uint32_t row = (uint32_t)i >> 9;
    // sign bit: 0x80000000 if parity odd, else 0
    uint32_t flip = (uint32_t)(__popc(row & MASK) & 1) << 31;

    float4 a = xr[i];
    float4 b = xi[i];

    uint32_t* pa = reinterpret_cast<uint32_t*>(&a);
    uint32_t* pb = reinterpret_cast<uint32_t*>(&b);
#pragma unroll
    for (int k = 0; k < 4; k++) { pa[k] ^= flip; pb[k] ^= flip; }

    outr[i] = a;
    outi[i] = b;
}

extern "C" void kernel_launch(void* const* d_in, const int* in_sizes, int n_in,
                              void* d_out, int out_size)
{
    const float4* xr = (const float4*)d_in[0];
    const float4* xi = (const float4*)d_in[1];
    float* out = (float*)d_out;
    float4* outr = (float4*)out;
    float4* outi = (float4*)(out + (size_t)N_ROWS * B_COLS);

    const int threads = 256;
    const int blocks = TOTAL4 / threads; // 8388608 / 256 = 32768, exact
    z_phase_kernel<<<blocks, threads>>>(xr, xi, outr, outi);
}